// round 12
// baseline (speedup 1.0000x reference)
#include <cuda_runtime.h>
#include <cuda_bf16.h>
#include <cstdint>
#include <math.h>

#define TOK 1024
#define NE 8
#define HD 1024
#define ID 768
#define NPAIR (2*TOK)

#define STG1 81920           // gemm1 stage: A 32KB + B(192 rows) 48KB
#define STG2 98304           // gemm2 stage: A 32KB + B(256 rows) 64KB

// ------------------------- device scratch (static, no allocs) -------------
__device__ int   g_cnt[NE];
__device__ int   g_bucket[NE][TOK];
__device__ float g_wt[NPAIR];

__device__ float xs[(size_t)TOK*HD];          // tf32-rounded x
__device__ float g_act[(size_t)NPAIR*ID];     // tf32-rounded activations
__device__ float g_os[(size_t)NPAIR*HD];      // per-slot outputs

// ------------------------- PTX helpers (baseline ISA only) ----------------
__device__ __forceinline__ uint32_t smem_u32(const void* p) {
    uint32_t a;
    asm("{ .reg .u64 t; cvta.to.shared.u64 t, %1; cvt.u32.u64 %0, t; }" : "=r"(a) : "l"(p));
    return a;
}
__device__ __forceinline__ void cp16(uint32_t dst, const void* src) {
    asm volatile("cp.async.cg.shared.global [%0], [%1], 16;" :: "r"(dst), "l"(src));
}
__device__ __forceinline__ void cp_commit() {
    asm volatile("cp.async.commit_group;");
}
__device__ __forceinline__ void ldsm4(uint32_t* r, uint32_t addr) {
    asm volatile("ldmatrix.sync.aligned.m8n8.x4.shared.b16 {%0,%1,%2,%3}, [%4];"
        : "=r"(r[0]), "=r"(r[1]), "=r"(r[2]), "=r"(r[3]) : "r"(addr));
}
__device__ __forceinline__ void mma_tf32(float* d, const uint32_t* a, uint32_t b0, uint32_t b1) {
    asm volatile("mma.sync.aligned.m16n8k8.row.col.f32.tf32.tf32.f32 "
        "{%0,%1,%2,%3}, {%4,%5,%6,%7}, {%8,%9}, {%0,%1,%2,%3};"
        : "+f"(d[0]), "+f"(d[1]), "+f"(d[2]), "+f"(d[3])
        : "r"(a[0]), "r"(a[1]), "r"(a[2]), "r"(a[3]), "r"(b0), "r"(b1));
}
__device__ __forceinline__ uint32_t to_tf32(float f) {
    uint32_t r;
    asm("cvt.rna.tf32.f32 %0, %1;" : "=r"(r) : "f"(f));
    return r;
}
__device__ __forceinline__ void sts128(uint32_t addr, uint4 v) {
    asm volatile("st.shared.v4.b32 [%0], {%1,%2,%3,%4};"
                 :: "r"(addr), "r"(v.x), "r"(v.y), "r"(v.z), "r"(v.w));
}

// ------------------------- routing ---------------------------------------
__global__ void routing_kernel(const float* __restrict__ rl) {
    int t = threadIdx.x;
    if (t < NE) g_cnt[t] = 0;
    __syncthreads();
    float l[NE];
#pragma unroll
    for (int e = 0; e < NE; e++) l[e] = rl[t * NE + e];
    int i0 = 0; float v0 = l[0];
#pragma unroll
    for (int e = 1; e < NE; e++) if (l[e] > v0) { v0 = l[e]; i0 = e; }
    int i1 = -1; float v1 = -3.4e38f;
#pragma unroll
    for (int e = 0; e < NE; e++) if (e != i0 && l[e] > v1) { v1 = l[e]; i1 = e; }
    float e1 = expf(v1 - v0);
    float inv = 1.0f / (1.0f + e1);
    int p0 = 2 * t, p1 = 2 * t + 1;
    g_wt[p0] = inv;
    g_wt[p1] = e1 * inv;
    int pos0 = atomicAdd(&g_cnt[i0], 1); g_bucket[i0][pos0] = p0;
    int pos1 = atomicAdd(&g_cnt[i1], 1); g_bucket[i1][pos1] = p1;
}

// ------------------------- x prepass: tf32 rounding -----------------------
__global__ void convert_x_kernel(const float* __restrict__ x) {
    size_t i4 = ((size_t)blockIdx.x * 256 + threadIdx.x) * 4;
    float4 v = *(const float4*)(x + i4);
    float4 o;
    o.x = __uint_as_float(to_tf32(v.x));
    o.y = __uint_as_float(to_tf32(v.y));
    o.z = __uint_as_float(to_tf32(v.z));
    o.w = __uint_as_float(to_tf32(v.w));
    *(float4*)(xs + i4) = o;
}

// ===========================================================================
// GEMM1: block tile 128(m) x 192(n = 96 gate + 96 up), K-chunk 64.
// 2 stages; A via cp.async from xs; B register-staged LDG -> dequant+tf32 ->
// STS interleaved with compute in quarters. One __syncthreads per chunk.
// 8 warps: mw = wid>>2 (2 x 64 m), nw = wid&3 (4 x 48 n).
// ===========================================================================
__global__ __launch_bounds__(256, 1) void gemm1_kernel(
    const float* __restrict__ w13, const float* __restrict__ w13s)
{
    int e  = blockIdx.z;
    int Me = g_cnt[e];
    int m0 = blockIdx.y * 128;
    if (m0 >= Me) return;
    int n0g = blockIdx.x * 96;

    extern __shared__ __align__(16) char dynraw[];
    __shared__ int s_tok[128];
    __shared__ int s_pair[128];

    int tid = threadIdx.x, wid = tid >> 5, lane = tid & 31;
    uint32_t dynb0 = smem_u32(dynraw);
    uint32_t dynb = (dynb0 + 1023u) & ~1023u;
    float* s_up = (float*)(dynraw + (dynb - dynb0));

    if (tid < 128) {
        int r = m0 + tid;
        int pr = (r < Me) ? g_bucket[e][r] : 0;
        s_pair[tid] = (r < Me) ? pr : -1;
        s_tok[tid]  = pr >> 1;
    }
    __syncthreads();

    // fill maps (affine in it; only A src needs per-it pointers)
    int row0 = tid >> 4, piece = tid & 15;
    const float* asrc[8];
#pragma unroll
    for (int it = 0; it < 8; it++)
        asrc[it] = xs + (size_t)s_tok[row0 + it * 16] * HD + piece * 4;
    uint32_t asdst0 = dynb + row0 * 256 + ((piece * 16) ^ ((row0 & 7) << 4));

    const float* bg = w13  + ((size_t)e * 2 * ID + n0g + row0) * HD + piece * 4;
    const float* bu = w13  + ((size_t)e * 2 * ID + ID + n0g + row0) * HD + piece * 4;
    const float* sg = w13s + ((size_t)e * 2 * ID + n0g + row0) * 8;
    const float* su = w13s + ((size_t)e * 2 * ID + ID + n0g + row0) * 8;
    uint32_t bdst0 = dynb + 32768 + row0 * 256 + ((piece * 16) ^ ((row0 & 7) << 4));

    // prologue: chunk 0 (B direct, A cp.async) -> stage 0
    float bs[12];
#pragma unroll
    for (int it = 0; it < 12; it++) bs[it] = (it < 6) ? sg[it * 128] : su[(it - 6) * 128];
#pragma unroll
    for (int it = 0; it < 12; it++) {
        const float* p = (it < 6) ? bg + it * (16 * HD) : bu + (it - 6) * (16 * HD);
        uint4 r = *(const uint4*)p, w;
        w.x = to_tf32(__uint_as_float(r.x) * bs[it]);
        w.y = to_tf32(__uint_as_float(r.y) * bs[it]);
        w.z = to_tf32(__uint_as_float(r.z) * bs[it]);
        w.w = to_tf32(__uint_as_float(r.w) * bs[it]);
        sts128(bdst0 + it * 4096, w);
    }
#pragma unroll
    for (int it = 0; it < 8; it++) cp16(asdst0 + it * 4096, asrc[it]);
    cp_commit();

    float acc[4][6][4] = {};
    int mw = wid >> 2, nw = wid & 3;
    uint32_t sw    = (lane & 7) << 4;
    uint32_t aBase = dynb + (uint32_t)(mw * 64 + ((lane >> 3) & 1) * 8 + (lane & 7)) * 256;
    uint32_t aK    = (lane >> 4) * 16;
    uint32_t bBase = dynb + 32768 + (uint32_t)(nw * 48 + (lane >> 4) * 8 + (lane & 7)) * 256;
    uint32_t bK    = ((lane >> 3) & 1) * 16;

    uint4 br[12];
    const int NC = HD / 64;   // 16
    for (int c = 0; c < NC; c++) {
        int st = c & 1;
        uint32_t ab = aBase + st * STG1, bb = bBase + st * STG1;
        asm volatile("cp.async.wait_group 0;");
        __syncthreads();
        bool pf = (c + 1 < NC);
        uint32_t so = (uint32_t)((c + 1) & 1) * STG1;
        uint32_t ko = (uint32_t)(c + 1) * 64;
        if (pf) {
            if (((c + 1) & 1) == 0) {
                int kb = (c + 1) >> 1;
#pragma unroll
                for (int it = 0; it < 12; it++)
                    bs[it] = (it < 6) ? sg[it * 128 + kb] : su[(it - 6) * 128 + kb];
            }
#pragma unroll
            for (int it = 0; it < 8; it++) cp16(asdst0 + it * 4096 + so, asrc[it] + ko);
        }
        cp_commit();

        auto KS = [&](int ks) {
            uint32_t A[4][4], B[3][4];
#pragma unroll
            for (int mt = 0; mt < 4; mt++)
                ldsm4(A[mt], ab + mt * 4096 + ((aK + ks * 32) ^ sw));
#pragma unroll
            for (int p = 0; p < 3; p++)
                ldsm4(B[p], bb + p * 4096 + ((bK + ks * 32) ^ sw));
#pragma unroll
            for (int mt = 0; mt < 4; mt++)
#pragma unroll
                for (int nt = 0; nt < 6; nt++)
                    mma_tf32(acc[mt][nt], A[mt], B[nt >> 1][(nt & 1) * 2], B[nt >> 1][(nt & 1) * 2 + 1]);
        };
        auto LDQ = [&](int q) {
#pragma unroll
            for (int j = 0; j < 3; j++) {
                int it = q * 3 + j;
                const float* p = (it < 6) ? bg + it * (16 * HD) : bu + (it - 6) * (16 * HD);
                br[it] = *(const uint4*)(p + ko);
            }
        };
        auto STQ = [&](int q) {
#pragma unroll
            for (int j = 0; j < 3; j++) {
                int it = q * 3 + j;
                uint4 r = br[it], w;
                w.x = to_tf32(__uint_as_float(r.x) * bs[it]);
                w.y = to_tf32(__uint_as_float(r.y) * bs[it]);
                w.z = to_tf32(__uint_as_float(r.z) * bs[it]);
                w.w = to_tf32(__uint_as_float(r.w) * bs[it]);
                sts128(bdst0 + it * 4096 + so, w);
            }
        };
        KS(0); if (pf) LDQ(0);
        KS(1); if (pf) LDQ(1);
        KS(2); if (pf) { STQ(0); LDQ(2); }
        KS(3); if (pf) { STQ(1); LDQ(3); }
        KS(4); if (pf) STQ(2);
        KS(5); if (pf) STQ(3);
        KS(6); KS(7);
    }

    // ---- epilogue: up warps (nw>=2) stash to smem, gate warps fuse silu ----
    int g2 = lane >> 2, t2 = (lane & 3) * 2;
    if (nw >= 2) {
#pragma unroll
        for (int mt = 0; mt < 4; mt++)
#pragma unroll
            for (int nt = 0; nt < 6; nt++) {
                int j = (nw - 2) * 48 + nt * 8 + t2;
                int r = mw * 64 + mt * 16 + g2;
                *(float2*)&s_up[r * 100 + j]       = make_float2(acc[mt][nt][0], acc[mt][nt][1]);
                *(float2*)&s_up[(r + 8) * 100 + j] = make_float2(acc[mt][nt][2], acc[mt][nt][3]);
            }
    }
    __syncthreads();
    if (nw < 2) {
#pragma unroll
        for (int mt = 0; mt < 4; mt++)
#pragma unroll
            for (int nt = 0; nt < 6; nt++) {
                int j = nw * 48 + nt * 8 + t2;
                int r0 = mw * 64 + mt * 16 + g2, r1 = r0 + 8;
                float2 u0 = *(float2*)&s_up[r0 * 100 + j];
                float2 u1 = *(float2*)&s_up[r1 * 100 + j];
                float g00 = acc[mt][nt][0], g01 = acc[mt][nt][1];
                float g10 = acc[mt][nt][2], g11 = acc[mt][nt][3];
                float a00 = u0.x * (g00 / (1.0f + __expf(-g00)));
                float a01 = u0.y * (g01 / (1.0f + __expf(-g01)));
                float a10 = u1.x * (g10 / (1.0f + __expf(-g10)));
                float a11 = u1.y * (g11 / (1.0f + __expf(-g11)));
                int p0 = s_pair[r0], p1 = s_pair[r1];
                if (p0 >= 0)
                    *(float2*)(g_act + (size_t)p0 * ID + n0g + j) = make_float2(
                        __uint_as_float(to_tf32(a00)), __uint_as_float(to_tf32(a01)));
                if (p1 >= 0)
                    *(float2*)(g_act + (size_t)p1 * ID + n0g + j) = make_float2(
                        __uint_as_float(to_tf32(a10)), __uint_as_float(to_tf32(a11)));
            }
    }
}

// ===========================================================================
// GEMM2: block tile 128(m) x 256(n), K-chunk 64, same pipeline shape.
// 8 warps: mw 2 x 64 m, nw 4 x 64 n.
// ===========================================================================
__global__ __launch_bounds__(256, 1) void gemm2_kernel(
    const float* __restrict__ w2, const float* __restrict__ w2s)
{
    int e  = blockIdx.z;
    int Me = g_cnt[e];
    int m0 = blockIdx.y * 128;
    if (m0 >= Me) return;
    int n0 = blockIdx.x * 256;

    extern __shared__ __align__(16) char dynraw[];
    __shared__ int s_arow[128];
    __shared__ int s_pair[128];

    int tid = threadIdx.x, wid = tid >> 5, lane = tid & 31;
    uint32_t dynb0 = smem_u32(dynraw);
    uint32_t dynb = (dynb0 + 1023u) & ~1023u;

    if (tid < 128) {
        int r = m0 + tid;
        int pr = (r < Me) ? g_bucket[e][r] : 0;
        s_pair[tid] = (r < Me) ? pr : -1;
        s_arow[tid] = pr;
    }
    __syncthreads();

    int row0 = tid >> 4, piece = tid & 15;
    const float* asrc[8];
#pragma unroll
    for (int it = 0; it < 8; it++)
        asrc[it] = g_act + (size_t)s_arow[row0 + it * 16] * ID + piece * 4;
    uint32_t asdst0 = dynb + row0 * 256 + ((piece * 16) ^ ((row0 & 7) << 4));

    const float* bb0 = w2  + ((size_t)e * HD + n0 + row0) * ID + piece * 4;
    const float* sb0 = w2s + ((size_t)e * HD + n0 + row0) * 6;
    uint32_t bdst0 = dynb + 32768 + row0 * 256 + ((piece * 16) ^ ((row0 & 7) << 4));

    float bs[16];
#pragma unroll
    for (int it = 0; it < 16; it++) bs[it] = sb0[it * 96];
#pragma unroll
    for (int it = 0; it < 16; it++) {
        uint4 r = *(const uint4*)(bb0 + it * (16 * ID)), w;
        w.x = to_tf32(__uint_as_float(r.x) * bs[it]);
        w.y = to_tf32(__uint_as_float(r.y) * bs[it]);
        w.z = to_tf32(__uint_as_float(r.z) * bs[it]);
        w.w = to_tf32(__uint_as_float(r.w) * bs[it]);
        sts128(bdst0 + it * 4096, w);
    }
#pragma unroll
    for (int it = 0; it < 8; it++) cp16(asdst0 + it * 4096, asrc[it]);
    cp_commit();

    float acc[4][8][4] = {};
    int mw = wid >> 2, nw = wid & 3;
    uint32_t sw    = (lane & 7) << 4;
    uint32_t aBase = dynb + (uint32_t)(mw * 64 + ((lane >> 3) & 1) * 8 + (lane & 7)) * 256;
    uint32_t aK    = (lane >> 4) * 16;
    uint32_t bBase = dynb + 32768 + (uint32_t)(nw * 64 + (lane >> 4) * 8 + (lane & 7)) * 256;
    uint32_t bK    = ((lane >> 3) & 1) * 16;

    uint4 br[16];
    const int NC = ID / 64;   // 12
    for (int c = 0; c < NC; c++) {
        int st = c & 1;
        uint32_t ab = aBase + st * STG2, bbs = bBase + st * STG2;
        asm volatile("cp.async.wait_group 0;");
        __syncthreads();
        bool pf = (c + 1 < NC);
        uint32_t so = (uint32_t)((c + 1) & 1) * STG2;
        uint32_t ko = (uint32_t)(c + 1) * 64;
        if (pf) {
            if (((c + 1) & 1) == 0) {
                int kb = (c + 1) >> 1;
#pragma unroll
                for (int it = 0; it < 16; it++) bs[it] = sb0[it * 96 + kb];
            }
#pragma unroll
            for (int it = 0; it < 8; it++) cp16(asdst0 + it * 4096 + so, asrc[it] + ko);
        }
        cp_commit();

        auto KS = [&](int ks) {
            uint32_t A[4][4], B[4][4];
#pragma unroll
            for (int mt = 0; mt < 4; mt++)
                ldsm4(A[mt], ab + mt * 4096 + ((aK + ks * 32) ^ sw));
#pragma unroll
            for (int p = 0; p < 4; p++)
                ldsm4(B[p], bbs + p * 4096 + ((bK + ks * 32) ^ sw));
#pragma unroll
            for (int mt = 0; mt < 4; mt++)
#pragma unroll
                for (int nt = 0; nt < 8; nt++)
                    mma_tf32(acc[mt][nt], A[mt], B[nt >> 1][(nt & 1) * 2], B[nt >> 1][(nt & 1) * 2 + 1]);
        };
        auto LDQ = [&](int q) {
#pragma unroll
            for (int j = 0; j < 4; j++) {
                int it = q * 4 + j;
                br[it] = *(const uint4*)(bb0 + it * (16 * ID) + ko);
            }
        };
        auto STQ = [&](int q) {
#pragma unroll
            for (int j = 0; j < 4; j++) {
                int it = q * 4 + j;
                uint4 r = br[it], w;
                w.x = to_tf32(__uint_as_float(r.x) * bs[it]);
                w.y = to_tf32(__uint_as_float(r.y) * bs[it]);
                w.z = to_tf32(__uint_as_float(r.z) * bs[it]);
                w.w = to_tf32(__uint_as_float(r.w) * bs[it]);
                sts128(bdst0 + it * 4096 + so, w);
            }
        };
        KS(0); if (pf) LDQ(0);
        KS(1); if (pf) LDQ(1);
        KS(2); if (pf) { STQ(0); LDQ(2); }
        KS(3); if (pf) { STQ(1); LDQ(3); }
        KS(4); if (pf) STQ(2);
        KS(5); if (pf) STQ(3);
        KS(6); KS(7);
    }

    // ---- epilogue: weighted store to per-slot planes ----
    int g2 = lane >> 2, t2 = (lane & 3) * 2;
#pragma unroll
    for (int mt = 0; mt < 4; mt++)
#pragma unroll
        for (int nt = 0; nt < 8; nt++) {
            int j = n0 + nw * 64 + nt * 8 + t2;
            int r0 = mw * 64 + mt * 16 + g2, r1 = r0 + 8;
            int p0 = s_pair[r0], p1 = s_pair[r1];
            if (p0 >= 0) {
                float wf = g_wt[p0];
                *(float2*)(g_os + (size_t)p0 * HD + j) =
                    make_float2(wf * acc[mt][nt][0], wf * acc[mt][nt][1]);
            }
            if (p1 >= 0) {
                float wf = g_wt[p1];
                *(float2*)(g_os + (size_t)p1 * HD + j) =
                    make_float2(wf * acc[mt][nt][2], wf * acc[mt][nt][3]);
            }
        }
}

// ------------------------- combine ----------------------------------------
__global__ void combine_kernel(float4* __restrict__ out) {
    int i = blockIdx.x * 256 + threadIdx.x;          // over TOK*HD/4
    int t = i >> 8;                                  // 256 float4 per row
    int h4 = i & 255;
    const float4* a = reinterpret_cast<const float4*>(g_os);
    float4 x = a[(size_t)(2 * t) * 256 + h4];
    float4 y = a[(size_t)(2 * t + 1) * 256 + h4];
    out[i] = make_float4(x.x + y.x, x.y + y.y, x.z + y.z, x.w + y.w);
}

// ------------------------- launch -----------------------------------------
extern "C" void kernel_launch(void* const* d_in, const int* in_sizes, int n_in,
                              void* d_out, int out_size) {
    const float* x    = (const float*)d_in[0];
    const float* rl   = (const float*)d_in[1];
    const float* w13  = (const float*)d_in[2];
    const float* w13s = (const float*)d_in[3];
    const float* w2   = (const float*)d_in[4];
    const float* w2s  = (const float*)d_in[5];
    float* out = (float*)d_out;

    const int DSM1 = 2 * STG1 + 1024;   // 164.8 KB
    const int DSM2 = 2 * STG2 + 1024;   // 197.6 KB
    cudaFuncSetAttribute(gemm1_kernel, cudaFuncAttributeMaxDynamicSharedMemorySize, DSM1);
    cudaFuncSetAttribute(gemm2_kernel, cudaFuncAttributeMaxDynamicSharedMemorySize, DSM2);

    routing_kernel<<<1, TOK>>>(rl);
    convert_x_kernel<<<(TOK * HD) / (256 * 4), 256>>>(x);

    dim3 g1(ID / 96, 8, NE);    // 8 x 8 x 8
    gemm1_kernel<<<g1, 256, DSM1>>>(w13, w13s);

    dim3 g2(HD / 256, 8, NE);   // 4 x 8 x 8
    gemm2_kernel<<<g2, 256, DSM2>>>(w2, w2s);

    combine_kernel<<<(TOK * HD) / (4 * 256), 256>>>(reinterpret_cast<float4*>(out));
}

// round 13
// speedup vs baseline: 1.7009x; 1.7009x over previous
#include <cuda_runtime.h>
#include <cuda_bf16.h>
#include <cstdint>
#include <math.h>

#define TOK 1024
#define NE 8
#define HD 1024
#define ID 768
#define NPAIR (2*TOK)

#define STAGE 65536          // per-stage smem: A 32KB + B 32KB
#define OPB   32768          // B offset within stage

// ------------------------- device scratch (static, no allocs) -------------
__device__ int   g_cnt[NE];
__device__ int   g_bucket[NE][TOK];
__device__ float g_wt[NPAIR];

__device__ float xs[(size_t)TOK*HD];          // tf32-rounded x
__device__ float g_act[(size_t)NPAIR*ID];     // tf32-rounded activations
__device__ float g_os[(size_t)NPAIR*HD];      // per-slot outputs

// ------------------------- PTX helpers (baseline ISA only) ----------------
__device__ __forceinline__ uint32_t smem_u32(const void* p) {
    uint32_t a;
    asm("{ .reg .u64 t; cvta.to.shared.u64 t, %1; cvt.u32.u64 %0, t; }" : "=r"(a) : "l"(p));
    return a;
}
__device__ __forceinline__ void cp16(uint32_t dst, const void* src) {
    asm volatile("cp.async.cg.shared.global [%0], [%1], 16;" :: "r"(dst), "l"(src));
}
__device__ __forceinline__ void cp_commit() {
    asm volatile("cp.async.commit_group;");
}
__device__ __forceinline__ void ldsm4(uint32_t* r, uint32_t addr) {
    asm volatile("ldmatrix.sync.aligned.m8n8.x4.shared.b16 {%0,%1,%2,%3}, [%4];"
        : "=r"(r[0]), "=r"(r[1]), "=r"(r[2]), "=r"(r[3]) : "r"(addr));
}
__device__ __forceinline__ void mma_tf32(float* d, const uint32_t* a, uint32_t b0, uint32_t b1) {
    asm volatile("mma.sync.aligned.m16n8k8.row.col.f32.tf32.tf32.f32 "
        "{%0,%1,%2,%3}, {%4,%5,%6,%7}, {%8,%9}, {%0,%1,%2,%3};"
        : "+f"(d[0]), "+f"(d[1]), "+f"(d[2]), "+f"(d[3])
        : "r"(a[0]), "r"(a[1]), "r"(a[2]), "r"(a[3]), "r"(b0), "r"(b1));
}
__device__ __forceinline__ uint32_t to_tf32(float f) {
    uint32_t r;
    asm("cvt.rna.tf32.f32 %0, %1;" : "=r"(r) : "f"(f));
    return r;
}
__device__ __forceinline__ void sts128(uint32_t addr, uint4 v) {
    asm volatile("st.shared.v4.b32 [%0], {%1,%2,%3,%4};"
                 :: "r"(addr), "r"(v.x), "r"(v.y), "r"(v.z), "r"(v.w));
}

// ------------------------- routing ---------------------------------------
__global__ void routing_kernel(const float* __restrict__ rl) {
    int t = threadIdx.x;
    if (t < NE) g_cnt[t] = 0;
    __syncthreads();
    float l[NE];
#pragma unroll
    for (int e = 0; e < NE; e++) l[e] = rl[t * NE + e];
    int i0 = 0; float v0 = l[0];
#pragma unroll
    for (int e = 1; e < NE; e++) if (l[e] > v0) { v0 = l[e]; i0 = e; }
    int i1 = -1; float v1 = -3.4e38f;
#pragma unroll
    for (int e = 0; e < NE; e++) if (e != i0 && l[e] > v1) { v1 = l[e]; i1 = e; }
    float e1 = expf(v1 - v0);
    float inv = 1.0f / (1.0f + e1);
    int p0 = 2 * t, p1 = 2 * t + 1;
    g_wt[p0] = inv;
    g_wt[p1] = e1 * inv;
    int pos0 = atomicAdd(&g_cnt[i0], 1); g_bucket[i0][pos0] = p0;
    int pos1 = atomicAdd(&g_cnt[i1], 1); g_bucket[i1][pos1] = p1;
}

// ------------------------- x prepass: tf32 rounding -----------------------
__global__ void convert_x_kernel(const float* __restrict__ x) {
    size_t i4 = ((size_t)blockIdx.x * 256 + threadIdx.x) * 4;
    float4 v = *(const float4*)(x + i4);
    float4 o;
    o.x = __uint_as_float(to_tf32(v.x));
    o.y = __uint_as_float(to_tf32(v.y));
    o.z = __uint_as_float(to_tf32(v.z));
    o.w = __uint_as_float(to_tf32(v.w));
    *(float4*)(xs + i4) = o;
}

// ===========================================================================
// GEMM geometry: block tile 128(m) x 128(n), K-chunk 64, 512 threads.
// 16 warps: mw = wid>>2 (4 x 32 m-rows), nw = wid&3 (4 x 32 n-cols).
// Warp tile 32x32 -> acc[2][4][4] = 32 regs. 2-stage pipeline:
// A via cp.async; B register-staged (4 x uint4/thread) with fused
// dequant + tf32 rounding (LDG overlapped with compute).
// smem row = 64 fp32 = 256B; swizzle off = row*256 + ((piece*16)^((row&7)<<4)).
// ===========================================================================

// ------------------------- GEMM1 (x @ w13^T, fused silu*up) ---------------
__global__ __launch_bounds__(512, 1) void gemm1_kernel(
    const float* __restrict__ w13, const float* __restrict__ w13s)
{
    int e  = blockIdx.z;
    int Me = g_cnt[e];
    int m0 = blockIdx.y * 128;
    if (m0 >= Me) return;
    int n0g = blockIdx.x * 64;

    extern __shared__ __align__(16) char dynraw[];
    __shared__ int s_tok[128];
    __shared__ int s_pair[128];

    int tid = threadIdx.x, wid = tid >> 5, lane = tid & 31;
    uint32_t dynb0 = smem_u32(dynraw);
    uint32_t dynb = (dynb0 + 1023u) & ~1023u;
    float* s_up = (float*)(dynraw + (dynb - dynb0));   // reused after mainloop

    if (tid < 128) {
        int r = m0 + tid;
        int pr = (r < Me) ? g_bucket[e][r] : 0;
        s_pair[tid] = (r < Me) ? pr : -1;
        s_tok[tid]  = pr >> 1;
    }
    __syncthreads();

    // fill maps: 4 tasks/thread; row = row0 + it*32, piece = tid&15
    int row0 = tid >> 4, piece = tid & 15;   // row0 0..31
    const float* asrc[4];
    const float* bgp[4];
    uint32_t bsoff[4];
#pragma unroll
    for (int it = 0; it < 4; it++) {
        int row = row0 + it * 32;
        asrc[it] = xs + (size_t)s_tok[row] * HD + piece * 4;
        int brow = (row < 64) ? (n0g + row) : (ID + n0g + (row - 64));
        bgp[it] = w13 + ((size_t)e * 2 * ID + brow) * HD + piece * 4;
        bsoff[it] = (uint32_t)(e * 2 * ID + brow) * (HD / 128);
    }
    uint32_t asd0 = dynb + row0 * 256 + ((piece * 16) ^ ((row0 & 7) << 4));
    uint32_t bsd0 = asd0 + OPB;

    // prologue: B(0) regs + scales, A(0) cp.async
    uint4 breg[4]; float bs[4];
#pragma unroll
    for (int it = 0; it < 4; it++) breg[it] = *(const uint4*)bgp[it];
#pragma unroll
    for (int it = 0; it < 4; it++) bs[it] = w13s[bsoff[it]];
#pragma unroll
    for (int it = 0; it < 4; it++) cp16(asd0 + it * 8192, asrc[it]);
    cp_commit();

    float acc[2][4][4] = {};
    int mw = wid >> 2, nw = wid & 3;
    uint32_t sw    = (lane & 7) << 4;
    uint32_t aBase = dynb + (uint32_t)(mw * 32 + ((lane >> 3) & 1) * 8 + (lane & 7)) * 256;
    uint32_t aK    = (lane >> 4) * 16;
    uint32_t bBase = dynb + OPB + (uint32_t)(nw * 32 + (lane >> 4) * 8 + (lane & 7)) * 256;
    uint32_t bK    = ((lane >> 3) & 1) * 16;

    const int NC = HD / 64;   // 16
    for (int c = 0; c < NC; c++) {
        int st = c & 1;
        uint32_t base = dynb + st * STAGE;
        // store B(c) with fused dequant + tf32 rounding
#pragma unroll
        for (int it = 0; it < 4; it++) {
            float s = bs[it];
            uint4 r = breg[it], w;
            w.x = to_tf32(__uint_as_float(r.x) * s);
            w.y = to_tf32(__uint_as_float(r.y) * s);
            w.z = to_tf32(__uint_as_float(r.z) * s);
            w.w = to_tf32(__uint_as_float(r.w) * s);
            sts128(bsd0 + it * 8192 + st * STAGE, w);
        }
        asm volatile("cp.async.wait_group 0;");
        __syncthreads();
        if (c + 1 < NC) {
            uint32_t ko = (uint32_t)(c + 1) * 64;
#pragma unroll
            for (int it = 0; it < 4; it++) breg[it] = *(const uint4*)(bgp[it] + ko);
            if (((c + 1) & 1) == 0) {
                int kb = (c + 1) >> 1;
#pragma unroll
                for (int it = 0; it < 4; it++) bs[it] = w13s[bsoff[it] + kb];
            }
            uint32_t so = (uint32_t)((c + 1) & 1) * STAGE;
#pragma unroll
            for (int it = 0; it < 4; it++) cp16(asd0 + it * 8192 + so, asrc[it] + ko);
            cp_commit();
        }
        uint32_t ab = aBase + st * STAGE, bb = bBase + st * STAGE;
#pragma unroll
        for (int ks = 0; ks < 8; ks++) {
            uint32_t A[2][4], B[2][4];
#pragma unroll
            for (int mt = 0; mt < 2; mt++)
                ldsm4(A[mt], ab + mt * 4096 + ((aK + ks * 32) ^ sw));
#pragma unroll
            for (int p = 0; p < 2; p++)
                ldsm4(B[p], bb + p * 4096 + ((bK + ks * 32) ^ sw));
#pragma unroll
            for (int mt = 0; mt < 2; mt++)
#pragma unroll
                for (int nt = 0; nt < 4; nt++)
                    mma_tf32(acc[mt][nt], A[mt], B[nt >> 1][(nt & 1) * 2], B[nt >> 1][(nt & 1) * 2 + 1]);
        }
        __syncthreads();
    }

    // ---- epilogue: up warps (nw>=2) stash to smem, gate warps fuse silu ----
    int g2 = lane >> 2, t2 = (lane & 3) * 2;
    if (nw >= 2) {
#pragma unroll
        for (int mt = 0; mt < 2; mt++)
#pragma unroll
            for (int nt = 0; nt < 4; nt++) {
                int j = (nw - 2) * 32 + nt * 8 + t2;
                int r = mw * 32 + mt * 16 + g2;
                *(float2*)&s_up[r * 66 + j]       = make_float2(acc[mt][nt][0], acc[mt][nt][1]);
                *(float2*)&s_up[(r + 8) * 66 + j] = make_float2(acc[mt][nt][2], acc[mt][nt][3]);
            }
    }
    __syncthreads();
    if (nw < 2) {
#pragma unroll
        for (int mt = 0; mt < 2; mt++)
#pragma unroll
            for (int nt = 0; nt < 4; nt++) {
                int j = nw * 32 + nt * 8 + t2;
                int r0 = mw * 32 + mt * 16 + g2, r1 = r0 + 8;
                float2 u0 = *(float2*)&s_up[r0 * 66 + j];
                float2 u1 = *(float2*)&s_up[r1 * 66 + j];
                float g00 = acc[mt][nt][0], g01 = acc[mt][nt][1];
                float g10 = acc[mt][nt][2], g11 = acc[mt][nt][3];
                float a00 = u0.x * (g00 / (1.0f + __expf(-g00)));
                float a01 = u0.y * (g01 / (1.0f + __expf(-g01)));
                float a10 = u1.x * (g10 / (1.0f + __expf(-g10)));
                float a11 = u1.y * (g11 / (1.0f + __expf(-g11)));
                int p0 = s_pair[r0], p1 = s_pair[r1];
                if (p0 >= 0)
                    *(float2*)(g_act + (size_t)p0 * ID + n0g + j) = make_float2(
                        __uint_as_float(to_tf32(a00)), __uint_as_float(to_tf32(a01)));
                if (p1 >= 0)
                    *(float2*)(g_act + (size_t)p1 * ID + n0g + j) = make_float2(
                        __uint_as_float(to_tf32(a10)), __uint_as_float(to_tf32(a11)));
            }
    }
}

// ------------------------- GEMM2 (act @ w2^T, weighted) -------------------
__global__ __launch_bounds__(512, 1) void gemm2_kernel(
    const float* __restrict__ w2, const float* __restrict__ w2s)
{
    int e  = blockIdx.z;
    int Me = g_cnt[e];
    int m0 = blockIdx.y * 128;
    if (m0 >= Me) return;
    int n0 = blockIdx.x * 128;

    extern __shared__ __align__(16) char dynraw[];
    __shared__ int s_arow[128];
    __shared__ int s_pair[128];

    int tid = threadIdx.x, wid = tid >> 5, lane = tid & 31;
    uint32_t dynb0 = smem_u32(dynraw);
    uint32_t dynb = (dynb0 + 1023u) & ~1023u;

    if (tid < 128) {
        int r = m0 + tid;
        int pr = (r < Me) ? g_bucket[e][r] : 0;
        s_pair[tid] = (r < Me) ? pr : -1;
        s_arow[tid] = pr;
    }
    __syncthreads();

    int row0 = tid >> 4, piece = tid & 15;
    const float* asrc[4];
    const float* bgp[4];
    uint32_t bsoff[4];
#pragma unroll
    for (int it = 0; it < 4; it++) {
        int row = row0 + it * 32;
        asrc[it] = g_act + (size_t)s_arow[row] * ID + piece * 4;
        bgp[it] = w2 + ((size_t)e * HD + n0 + row) * ID + piece * 4;
        bsoff[it] = (uint32_t)(e * HD + n0 + row) * (ID / 128);
    }
    uint32_t asd0 = dynb + row0 * 256 + ((piece * 16) ^ ((row0 & 7) << 4));
    uint32_t bsd0 = asd0 + OPB;

    uint4 breg[4]; float bs[4];
#pragma unroll
    for (int it = 0; it < 4; it++) breg[it] = *(const uint4*)bgp[it];
#pragma unroll
    for (int it = 0; it < 4; it++) bs[it] = w2s[bsoff[it]];
#pragma unroll
    for (int it = 0; it < 4; it++) cp16(asd0 + it * 8192, asrc[it]);
    cp_commit();

    float acc[2][4][4] = {};
    int mw = wid >> 2, nw = wid & 3;
    uint32_t sw    = (lane & 7) << 4;
    uint32_t aBase = dynb + (uint32_t)(mw * 32 + ((lane >> 3) & 1) * 8 + (lane & 7)) * 256;
    uint32_t aK    = (lane >> 4) * 16;
    uint32_t bBase = dynb + OPB + (uint32_t)(nw * 32 + (lane >> 4) * 8 + (lane & 7)) * 256;
    uint32_t bK    = ((lane >> 3) & 1) * 16;

    const int NC = ID / 64;   // 12
    for (int c = 0; c < NC; c++) {
        int st = c & 1;
#pragma unroll
        for (int it = 0; it < 4; it++) {
            float s = bs[it];
            uint4 r = breg[it], w;
            w.x = to_tf32(__uint_as_float(r.x) * s);
            w.y = to_tf32(__uint_as_float(r.y) * s);
            w.z = to_tf32(__uint_as_float(r.z) * s);
            w.w = to_tf32(__uint_as_float(r.w) * s);
            sts128(bsd0 + it * 8192 + st * STAGE, w);
        }
        asm volatile("cp.async.wait_group 0;");
        __syncthreads();
        if (c + 1 < NC) {
            uint32_t ko = (uint32_t)(c + 1) * 64;
#pragma unroll
            for (int it = 0; it < 4; it++) breg[it] = *(const uint4*)(bgp[it] + ko);
            if (((c + 1) & 1) == 0) {
                int kb = (c + 1) >> 1;
#pragma unroll
                for (int it = 0; it < 4; it++) bs[it] = w2s[bsoff[it] + kb];
            }
            uint32_t so = (uint32_t)((c + 1) & 1) * STAGE;
#pragma unroll
            for (int it = 0; it < 4; it++) cp16(asd0 + it * 8192 + so, asrc[it] + ko);
            cp_commit();
        }
        uint32_t ab = aBase + st * STAGE, bb = bBase + st * STAGE;
#pragma unroll
        for (int ks = 0; ks < 8; ks++) {
            uint32_t A[2][4], B[2][4];
#pragma unroll
            for (int mt = 0; mt < 2; mt++)
                ldsm4(A[mt], ab + mt * 4096 + ((aK + ks * 32) ^ sw));
#pragma unroll
            for (int p = 0; p < 2; p++)
                ldsm4(B[p], bb + p * 4096 + ((bK + ks * 32) ^ sw));
#pragma unroll
            for (int mt = 0; mt < 2; mt++)
#pragma unroll
                for (int nt = 0; nt < 4; nt++)
                    mma_tf32(acc[mt][nt], A[mt], B[nt >> 1][(nt & 1) * 2], B[nt >> 1][(nt & 1) * 2 + 1]);
        }
        __syncthreads();
    }

    // ---- epilogue: weighted store to per-slot planes ----
    int g2 = lane >> 2, t2 = (lane & 3) * 2;
#pragma unroll
    for (int mt = 0; mt < 2; mt++)
#pragma unroll
        for (int nt = 0; nt < 4; nt++) {
            int j = n0 + nw * 32 + nt * 8 + t2;
            int r0 = mw * 32 + mt * 16 + g2, r1 = r0 + 8;
            int p0 = s_pair[r0], p1 = s_pair[r1];
            if (p0 >= 0) {
                float wf = g_wt[p0];
                *(float2*)(g_os + (size_t)p0 * HD + j) =
                    make_float2(wf * acc[mt][nt][0], wf * acc[mt][nt][1]);
            }
            if (p1 >= 0) {
                float wf = g_wt[p1];
                *(float2*)(g_os + (size_t)p1 * HD + j) =
                    make_float2(wf * acc[mt][nt][2], wf * acc[mt][nt][3]);
            }
        }
}

// ------------------------- combine ----------------------------------------
__global__ void combine_kernel(float4* __restrict__ out) {
    int i = blockIdx.x * 256 + threadIdx.x;          // over TOK*HD/4
    int t = i >> 8;                                  // 256 float4 per row
    int h4 = i & 255;
    const float4* a = reinterpret_cast<const float4*>(g_os);
    float4 x = a[(size_t)(2 * t) * 256 + h4];
    float4 y = a[(size_t)(2 * t + 1) * 256 + h4];
    out[i] = make_float4(x.x + y.x, x.y + y.y, x.z + y.z, x.w + y.w);
}

// ------------------------- launch -----------------------------------------
extern "C" void kernel_launch(void* const* d_in, const int* in_sizes, int n_in,
                              void* d_out, int out_size) {
    const float* x    = (const float*)d_in[0];
    const float* rl   = (const float*)d_in[1];
    const float* w13  = (const float*)d_in[2];
    const float* w13s = (const float*)d_in[3];
    const float* w2   = (const float*)d_in[4];
    const float* w2s  = (const float*)d_in[5];
    float* out = (float*)d_out;

    const int DSM = 2 * STAGE + 1024;   // 132 KB
    cudaFuncSetAttribute(gemm1_kernel, cudaFuncAttributeMaxDynamicSharedMemorySize, DSM);
    cudaFuncSetAttribute(gemm2_kernel, cudaFuncAttributeMaxDynamicSharedMemorySize, DSM);

    routing_kernel<<<1, TOK>>>(rl);
    convert_x_kernel<<<(TOK * HD) / (256 * 4), 256>>>(x);

    dim3 g1(ID / 64, 8, NE);    // 12 x 8 x 8 (m-tiles beyond Me early-exit)
    gemm1_kernel<<<g1, 512, DSM>>>(w13, w13s);

    dim3 g2(HD / 128, 8, NE);   // 8 x 8 x 8
    gemm2_kernel<<<g2, 512, DSM>>>(w2, w2s);

    combine_kernel<<<(TOK * HD) / (4 * 256), 256>>>(reinterpret_cast<float4*>(out));
}

// round 16
// speedup vs baseline: 1.7278x; 1.0158x over previous
#include <cuda_runtime.h>
#include <cuda_bf16.h>
#include <cstdint>
#include <math.h>

#define TOK 1024
#define NE 8
#define HD 1024
#define ID 768
#define NPAIR (2*TOK)

#define STAGE 65536          // per-stage smem: A 32KB + B 32KB
#define OPB   32768          // B offset within stage

// ------------------------- device scratch (static, no allocs) -------------
__device__ int   g_cnt[NE];
__device__ int   g_bucket[NE][TOK];
__device__ float g_wt[NPAIR];

__device__ float xs[(size_t)TOK*HD];          // tf32-rounded x
__device__ float g_act[(size_t)NPAIR*ID];     // tf32-rounded activations
__device__ float g_os[(size_t)NPAIR*HD];      // per-slot outputs

// persistent-scheduler state (reset by routing kernel every launch)
__device__ int g_next, g_total;
__device__ int g_items[2048];
__device__ int g1done[NE], g1need[NE];

// ------------------------- PTX helpers (baseline ISA only) ----------------
__device__ __forceinline__ uint32_t smem_u32(const void* p) {
    uint32_t a;
    asm("{ .reg .u64 t; cvta.to.shared.u64 t, %1; cvt.u32.u64 %0, t; }" : "=r"(a) : "l"(p));
    return a;
}
__device__ __forceinline__ void cp16(uint32_t dst, const void* src) {
    asm volatile("cp.async.cg.shared.global [%0], [%1], 16;" :: "r"(dst), "l"(src));
}
__device__ __forceinline__ void cp_commit() {
    asm volatile("cp.async.commit_group;");
}
__device__ __forceinline__ void ldsm4(uint32_t* r, uint32_t addr) {
    asm volatile("ldmatrix.sync.aligned.m8n8.x4.shared.b16 {%0,%1,%2,%3}, [%4];"
        : "=r"(r[0]), "=r"(r[1]), "=r"(r[2]), "=r"(r[3]) : "r"(addr));
}
__device__ __forceinline__ void mma_tf32(float* d, const uint32_t* a, uint32_t b0, uint32_t b1) {
    asm volatile("mma.sync.aligned.m16n8k8.row.col.f32.tf32.tf32.f32 "
        "{%0,%1,%2,%3}, {%4,%5,%6,%7}, {%8,%9}, {%0,%1,%2,%3};"
        : "+f"(d[0]), "+f"(d[1]), "+f"(d[2]), "+f"(d[3])
        : "r"(a[0]), "r"(a[1]), "r"(a[2]), "r"(a[3]), "r"(b0), "r"(b1));
}
__device__ __forceinline__ uint32_t to_tf32(float f) {
    uint32_t r;
    asm("cvt.rna.tf32.f32 %0, %1;" : "=r"(r) : "f"(f));
    return r;
}
__device__ __forceinline__ void sts128(uint32_t addr, uint4 v) {
    asm volatile("st.shared.v4.b32 [%0], {%1,%2,%3,%4};"
                 :: "r"(addr), "r"(v.x), "r"(v.y), "r"(v.z), "r"(v.w));
}

// ------------------------- routing + planner ------------------------------
__global__ void routing_kernel(const float* __restrict__ rl) {
    int t = threadIdx.x;
    if (t < NE) g_cnt[t] = 0;
    __syncthreads();
    float l[NE];
#pragma unroll
    for (int e = 0; e < NE; e++) l[e] = rl[t * NE + e];
    int i0 = 0; float v0 = l[0];
#pragma unroll
    for (int e = 1; e < NE; e++) if (l[e] > v0) { v0 = l[e]; i0 = e; }
    int i1 = -1; float v1 = -3.4e38f;
#pragma unroll
    for (int e = 0; e < NE; e++) if (e != i0 && l[e] > v1) { v1 = l[e]; i1 = e; }
    float e1 = expf(v1 - v0);
    float inv = 1.0f / (1.0f + e1);
    int p0 = 2 * t, p1 = 2 * t + 1;
    g_wt[p0] = inv;
    g_wt[p1] = e1 * inv;
    int pos0 = atomicAdd(&g_cnt[i0], 1); g_bucket[i0][pos0] = p0;
    int pos1 = atomicAdd(&g_cnt[i1], 1); g_bucket[i1][pos1] = p1;

    // ---- planner: build work-item list (phase1 tiles, then phase2 tiles) ----
    __syncthreads();
    __shared__ int s_b1[NE + 1], s_b2[NE + 1];
    if (t == 0) {
        int b1 = 0, b2 = 0;
        for (int e = 0; e < NE; e++) {
            int yt = (g_cnt[e] + 127) >> 7;
            s_b1[e] = b1; s_b2[e] = b2;
            g1need[e] = yt * (ID / 64);   // 12 n-tiles in gemm1
            g1done[e] = 0;
            b1 += yt * (ID / 64);
            b2 += yt * (HD / 128);        // 8 n-tiles in gemm2
        }
        s_b1[NE] = b1; s_b2[NE] = b2;
        g_total = b1 + b2;
        g_next  = 0;
    }
    __syncthreads();
    int tot1 = s_b1[NE], tot2 = s_b2[NE];
    for (int i = t; i < tot1; i += TOK) {
        int e = 0;
        while (i >= s_b1[e + 1]) e++;
        int loc = i - s_b1[e];
        g_items[i] = (0 << 28) | (e << 24) | ((loc / 12) << 16) | (loc % 12);
    }
    for (int i = t; i < tot2; i += TOK) {
        int e = 0;
        while (i >= s_b2[e + 1]) e++;
        int loc = i - s_b2[e];
        g_items[tot1 + i] = (1 << 28) | (e << 24) | ((loc / 8) << 16) | (loc % 8);
    }
}

// ------------------------- x prepass: tf32 rounding -----------------------
__global__ void convert_x_kernel(const float* __restrict__ x) {
    size_t i4 = ((size_t)blockIdx.x * 256 + threadIdx.x) * 4;
    float4 v = *(const float4*)(x + i4);
    float4 o;
    o.x = __uint_as_float(to_tf32(v.x));
    o.y = __uint_as_float(to_tf32(v.y));
    o.z = __uint_as_float(to_tf32(v.z));
    o.w = __uint_as_float(to_tf32(v.w));
    *(float4*)(xs + i4) = o;
}

// ===========================================================================
// Persistent fused GEMM kernel. 512 threads, 16 warps (mw 4x32m, nw 4x32n),
// warp tile 32x32, acc[2][4][4]. Block tile 128x128, K-chunk 64, 2 stages.
// A via cp.async; B register-staged with fused dequant + tf32 rounding.
// Work items pulled from g_items via g_next; phase2 items spin on g1done[e].
// ===========================================================================
__global__ __launch_bounds__(512, 1) void moe_gemms(
    const float* __restrict__ w13, const float* __restrict__ w13s,
    const float* __restrict__ w2,  const float* __restrict__ w2s)
{
    extern __shared__ __align__(16) char dynraw[];
    __shared__ int s_row[128];    // token (g1) or pair (g2) source row
    __shared__ int s_pair[128];
    __shared__ int s_item;

    int tid = threadIdx.x, wid = tid >> 5, lane = tid & 31;
    uint32_t dynb0 = smem_u32(dynraw);
    uint32_t dynb = (dynb0 + 1023u) & ~1023u;
    float* s_up = (float*)(dynraw + (dynb - dynb0));

    int row0 = tid >> 4, piece = tid & 15;
    uint32_t asd0 = dynb + row0 * 256 + ((piece * 16) ^ ((row0 & 7) << 4));
    uint32_t bsd0 = asd0 + OPB;

    int mw = wid >> 2, nw = wid & 3;
    uint32_t sw    = (lane & 7) << 4;
    uint32_t aBase = dynb + (uint32_t)(mw * 32 + ((lane >> 3) & 1) * 8 + (lane & 7)) * 256;
    uint32_t aK    = (lane >> 4) * 16;
    uint32_t bBase = dynb + OPB + (uint32_t)(nw * 32 + (lane >> 4) * 8 + (lane & 7)) * 256;
    uint32_t bK    = ((lane >> 3) & 1) * 16;
    int g2l = lane >> 2, t2 = (lane & 3) * 2;

    for (;;) {
        if (tid == 0) {
            int idx = atomicAdd(&g_next, 1);
            s_item = (idx < g_total) ? g_items[idx] : -1;
        }
        __syncthreads();
        int item = s_item;
        __syncthreads();
        if (item < 0) break;
        int ph = item >> 28;
        int e  = (item >> 24) & 15;
        int m0 = ((item >> 16) & 255) * 128;
        int ntile = item & 65535;
        int Me = g_cnt[e];

        if (ph == 0) {
            // =============== GEMM1 tile: x @ w13^T, fused silu*up ===============
            int n0g = ntile * 64;
            if (tid < 128) {
                int r = m0 + tid;
                int pr = (r < Me) ? g_bucket[e][r] : 0;
                s_pair[tid] = (r < Me) ? pr : -1;
                s_row[tid]  = pr >> 1;
            }
            __syncthreads();

            const float* asrc[4];
            const float* bgp[4];
            uint32_t bsoff[4];
#pragma unroll
            for (int it = 0; it < 4; it++) {
                int row = row0 + it * 32;
                asrc[it] = xs + (size_t)s_row[row] * HD + piece * 4;
                int brow = (row < 64) ? (n0g + row) : (ID + n0g + (row - 64));
                bgp[it] = w13 + ((size_t)e * 2 * ID + brow) * HD + piece * 4;
                bsoff[it] = (uint32_t)(e * 2 * ID + brow) * (HD / 128);
            }

            uint4 breg[4]; float bs[4];
#pragma unroll
            for (int it = 0; it < 4; it++) breg[it] = *(const uint4*)bgp[it];
#pragma unroll
            for (int it = 0; it < 4; it++) bs[it] = w13s[bsoff[it]];
#pragma unroll
            for (int it = 0; it < 4; it++) cp16(asd0 + it * 8192, asrc[it]);
            cp_commit();

            float acc[2][4][4] = {};
            const int NC = HD / 64;   // 16
            for (int c = 0; c < NC; c++) {
                int st = c & 1;
#pragma unroll
                for (int it = 0; it < 4; it++) {
                    float s = bs[it];
                    uint4 r = breg[it], w;
                    w.x = to_tf32(__uint_as_float(r.x) * s);
                    w.y = to_tf32(__uint_as_float(r.y) * s);
                    w.z = to_tf32(__uint_as_float(r.z) * s);
                    w.w = to_tf32(__uint_as_float(r.w) * s);
                    sts128(bsd0 + it * 8192 + st * STAGE, w);
                }
                asm volatile("cp.async.wait_group 0;");
                __syncthreads();
                if (c + 1 < NC) {
                    uint32_t ko = (uint32_t)(c + 1) * 64;
#pragma unroll
                    for (int it = 0; it < 4; it++) breg[it] = *(const uint4*)(bgp[it] + ko);
                    if (((c + 1) & 1) == 0) {
                        int kb = (c + 1) >> 1;
#pragma unroll
                        for (int it = 0; it < 4; it++) bs[it] = w13s[bsoff[it] + kb];
                    }
                    uint32_t so = (uint32_t)((c + 1) & 1) * STAGE;
#pragma unroll
                    for (int it = 0; it < 4; it++) cp16(asd0 + it * 8192 + so, asrc[it] + ko);
                    cp_commit();
                }
                uint32_t ab = aBase + st * STAGE, bb = bBase + st * STAGE;
#pragma unroll
                for (int ks = 0; ks < 8; ks++) {
                    uint32_t A[2][4], B[2][4];
#pragma unroll
                    for (int mt = 0; mt < 2; mt++)
                        ldsm4(A[mt], ab + mt * 4096 + ((aK + ks * 32) ^ sw));
#pragma unroll
                    for (int p = 0; p < 2; p++)
                        ldsm4(B[p], bb + p * 4096 + ((bK + ks * 32) ^ sw));
#pragma unroll
                    for (int mt = 0; mt < 2; mt++)
#pragma unroll
                        for (int nt = 0; nt < 4; nt++)
                            mma_tf32(acc[mt][nt], A[mt], B[nt >> 1][(nt & 1) * 2], B[nt >> 1][(nt & 1) * 2 + 1]);
                }
                __syncthreads();
            }

            // epilogue: up warps stash, gate warps fuse silu
            if (nw >= 2) {
#pragma unroll
                for (int mt = 0; mt < 2; mt++)
#pragma unroll
                    for (int nt = 0; nt < 4; nt++) {
                        int j = (nw - 2) * 32 + nt * 8 + t2;
                        int r = mw * 32 + mt * 16 + g2l;
                        *(float2*)&s_up[r * 66 + j]       = make_float2(acc[mt][nt][0], acc[mt][nt][1]);
                        *(float2*)&s_up[(r + 8) * 66 + j] = make_float2(acc[mt][nt][2], acc[mt][nt][3]);
                    }
            }
            __syncthreads();
            if (nw < 2) {
#pragma unroll
                for (int mt = 0; mt < 2; mt++)
#pragma unroll
                    for (int nt = 0; nt < 4; nt++) {
                        int j = nw * 32 + nt * 8 + t2;
                        int r0 = mw * 32 + mt * 16 + g2l, r1 = r0 + 8;
                        float2 u0 = *(float2*)&s_up[r0 * 66 + j];
                        float2 u1 = *(float2*)&s_up[r1 * 66 + j];
                        float g00 = acc[mt][nt][0], g01 = acc[mt][nt][1];
                        float g10 = acc[mt][nt][2], g11 = acc[mt][nt][3];
                        float a00 = u0.x * (g00 / (1.0f + __expf(-g00)));
                        float a01 = u0.y * (g01 / (1.0f + __expf(-g01)));
                        float a10 = u1.x * (g10 / (1.0f + __expf(-g10)));
                        float a11 = u1.y * (g11 / (1.0f + __expf(-g11)));
                        int p0 = s_pair[r0], p1 = s_pair[r1];
                        if (p0 >= 0)
                            *(float2*)(g_act + (size_t)p0 * ID + n0g + j) = make_float2(
                                __uint_as_float(to_tf32(a00)), __uint_as_float(to_tf32(a01)));
                        if (p1 >= 0)
                            *(float2*)(g_act + (size_t)p1 * ID + n0g + j) = make_float2(
                                __uint_as_float(to_tf32(a10)), __uint_as_float(to_tf32(a11)));
                    }
            }
            __threadfence();
            __syncthreads();
            if (tid == 0) atomicAdd(&g1done[e], 1);
        } else {
            // =============== GEMM2 tile: act @ w2^T, weighted ===============
            int n0 = ntile * 128;
            if (tid == 0) {
                int need = g1need[e];
                while (*(volatile int*)&g1done[e] < need) { }
            }
            __syncthreads();
            __threadfence();

            if (tid < 128) {
                int r = m0 + tid;
                int pr = (r < Me) ? g_bucket[e][r] : 0;
                s_pair[tid] = (r < Me) ? pr : -1;
                s_row[tid]  = pr;
            }
            __syncthreads();

            const float* asrc[4];
            const float* bgp[4];
            uint32_t bsoff[4];
#pragma unroll
            for (int it = 0; it < 4; it++) {
                int row = row0 + it * 32;
                asrc[it] = g_act + (size_t)s_row[row] * ID + piece * 4;
                bgp[it] = w2 + ((size_t)e * HD + n0 + row) * ID + piece * 4;
                bsoff[it] = (uint32_t)(e * HD + n0 + row) * (ID / 128);
            }

            uint4 breg[4]; float bs[4];
#pragma unroll
            for (int it = 0; it < 4; it++) breg[it] = *(const uint4*)bgp[it];
#pragma unroll
            for (int it = 0; it < 4; it++) bs[it] = w2s[bsoff[it]];
#pragma unroll
            for (int it = 0; it < 4; it++) cp16(asd0 + it * 8192, asrc[it]);
            cp_commit();

            float acc[2][4][4] = {};
            const int NC = ID / 64;   // 12
            for (int c = 0; c < NC; c++) {
                int st = c & 1;
#pragma unroll
                for (int it = 0; it < 4; it++) {
                    float s = bs[it];
                    uint4 r = breg[it], w;
                    w.x = to_tf32(__uint_as_float(r.x) * s);
                    w.y = to_tf32(__uint_as_float(r.y) * s);
                    w.z = to_tf32(__uint_as_float(r.z) * s);
                    w.w = to_tf32(__uint_as_float(r.w) * s);
                    sts128(bsd0 + it * 8192 + st * STAGE, w);
                }
                asm volatile("cp.async.wait_group 0;");
                __syncthreads();
                if (c + 1 < NC) {
                    uint32_t ko = (uint32_t)(c + 1) * 64;
#pragma unroll
                    for (int it = 0; it < 4; it++) breg[it] = *(const uint4*)(bgp[it] + ko);
                    if (((c + 1) & 1) == 0) {
                        int kb = (c + 1) >> 1;
#pragma unroll
                        for (int it = 0; it < 4; it++) bs[it] = w2s[bsoff[it] + kb];
                    }
                    uint32_t so = (uint32_t)((c + 1) & 1) * STAGE;
#pragma unroll
                    for (int it = 0; it < 4; it++) cp16(asd0 + it * 8192 + so, asrc[it] + ko);
                    cp_commit();
                }
                uint32_t ab = aBase + st * STAGE, bb = bBase + st * STAGE;
#pragma unroll
                for (int ks = 0; ks < 8; ks++) {
                    uint32_t A[2][4], B[2][4];
#pragma unroll
                    for (int mt = 0; mt < 2; mt++)
                        ldsm4(A[mt], ab + mt * 4096 + ((aK + ks * 32) ^ sw));
#pragma unroll
                    for (int p = 0; p < 2; p++)
                        ldsm4(B[p], bb + p * 4096 + ((bK + ks * 32) ^ sw));
#pragma unroll
                    for (int mt = 0; mt < 2; mt++)
#pragma unroll
                        for (int nt = 0; nt < 4; nt++)
                            mma_tf32(acc[mt][nt], A[mt], B[nt >> 1][(nt & 1) * 2], B[nt >> 1][(nt & 1) * 2 + 1]);
                }
                __syncthreads();
            }

            // epilogue: weighted store to per-slot planes
#pragma unroll
            for (int mt = 0; mt < 2; mt++)
#pragma unroll
                for (int nt = 0; nt < 4; nt++) {
                    int j = n0 + nw * 32 + nt * 8 + t2;
                    int r0 = mw * 32 + mt * 16 + g2l, r1 = r0 + 8;
                    int p0 = s_pair[r0], p1 = s_pair[r1];
                    if (p0 >= 0) {
                        float wf = g_wt[p0];
                        *(float2*)(g_os + (size_t)p0 * HD + j) =
                            make_float2(wf * acc[mt][nt][0], wf * acc[mt][nt][1]);
                    }
                    if (p1 >= 0) {
                        float wf = g_wt[p1];
                        *(float2*)(g_os + (size_t)p1 * HD + j) =
                            make_float2(wf * acc[mt][nt][2], wf * acc[mt][nt][3]);
                    }
                }
            __syncthreads();
        }
    }
}

// ------------------------- combine ----------------------------------------
__global__ void combine_kernel(float4* __restrict__ out) {
    int i = blockIdx.x * 256 + threadIdx.x;          // over TOK*HD/4
    int t = i >> 8;                                  // 256 float4 per row
    int h4 = i & 255;
    const float4* a = reinterpret_cast<const float4*>(g_os);
    float4 x = a[(size_t)(2 * t) * 256 + h4];
    float4 y = a[(size_t)(2 * t + 1) * 256 + h4];
    out[i] = make_float4(x.x + y.x, x.y + y.y, x.z + y.z, x.w + y.w);
}

// ------------------------- launch -----------------------------------------
extern "C" void kernel_launch(void* const* d_in, const int* in_sizes, int n_in,
                              void* d_out, int out_size) {
    const float* x    = (const float*)d_in[0];
    const float* rl   = (const float*)d_in[1];
    const float* w13  = (const float*)d_in[2];
    const float* w13s = (const float*)d_in[3];
    const float* w2   = (const float*)d_in[4];
    const float* w2s  = (const float*)d_in[5];
    float* out = (float*)d_out;

    const int DSM = 2 * STAGE + 1024;   // 132 KB
    cudaFuncSetAttribute(moe_gemms, cudaFuncAttributeMaxDynamicSharedMemorySize, DSM);

    routing_kernel<<<1, TOK>>>(rl);
    convert_x_kernel<<<(TOK * HD) / (256 * 4), 256>>>(x);

    moe_gemms<<<152, 512, DSM>>>(w13, w13s, w2, w2s);

    combine_kernel<<<(TOK * HD) / (4 * 256), 256>>>(reinterpret_cast<float4*>(out));
}